// round 3
// baseline (speedup 1.0000x reference)
#include <cuda_runtime.h>
#include <cstdint>

#define N_NODES 100000
#define N_EDGES 1250000
#define IN_CH   128
#define HID_CH  64
#define CLS_CH  32
#define SCAN_B  1024
#define NB      98        // ceil(N_NODES / SCAN_B)

// ---------------- scratch (device globals; alloc-free rule) ----------------
__device__ __align__(16) float g_h1  [(size_t)N_NODES * HID_CH]; // x @ W1
__device__ __align__(16) float g_act1[(size_t)N_NODES * HID_CH]; // relu(A@h1 + b1)
__device__ __align__(16) float g_m2  [(size_t)N_NODES * CLS_CH]; // act1 @ W2
__device__ int g_deg   [N_NODES];
__device__ int g_incl  [N_NODES];
__device__ int g_off   [N_NODES];
__device__ int g_cursor[N_NODES];
__device__ int g_bsum  [128];
__device__ int g_csr_src[N_EDGES];

// ---------------- packed f32x2 helpers ----------------
__device__ __forceinline__ unsigned long long pack2(float a, float b) {
    unsigned long long r;
    asm("mov.b64 %0, {%1, %2};" : "=l"(r) : "f"(a), "f"(b));
    return r;
}
__device__ __forceinline__ unsigned long long fma2(unsigned long long a,
                                                   unsigned long long b,
                                                   unsigned long long c) {
    unsigned long long d;
    asm("fma.rn.f32x2 %0, %1, %2, %3;" : "=l"(d) : "l"(a), "l"(b), "l"(c));
    return d;
}

// ---------------- CSR build ----------------
__global__ void k_zero_cnt() {
    int i = blockIdx.x * blockDim.x + threadIdx.x;
    if (i < N_NODES) { g_deg[i] = 0; g_cursor[i] = 0; }
}

__global__ void k_hist(const int* __restrict__ dst) {
    int e = blockIdx.x * blockDim.x + threadIdx.x;
    if (e < N_EDGES) atomicAdd(&g_deg[__ldg(dst + e)], 1);
}

__global__ __launch_bounds__(SCAN_B) void k_scan1() {
    __shared__ int s[SCAN_B];
    int tid = threadIdx.x;
    int i = blockIdx.x * SCAN_B + tid;
    int v = (i < N_NODES) ? g_deg[i] : 0;
    s[tid] = v;
    __syncthreads();
#pragma unroll
    for (int ofs = 1; ofs < SCAN_B; ofs <<= 1) {
        int t = (tid >= ofs) ? s[tid - ofs] : 0;
        __syncthreads();
        s[tid] += t;
        __syncthreads();
    }
    if (i < N_NODES) g_incl[i] = s[tid];
    if (tid == SCAN_B - 1) g_bsum[blockIdx.x] = s[tid];
}

// merged scan2+scan3: each block reduces block-sums below it, then finalizes offsets
__global__ __launch_bounds__(SCAN_B) void k_scan23() {
    __shared__ int sred[32];
    __shared__ int s_base;
    int tid = threadIdx.x;
    int v = (tid < blockIdx.x) ? g_bsum[tid] : 0;   // blockIdx.x <= 97 < 128
#pragma unroll
    for (int o = 16; o; o >>= 1) v += __shfl_down_sync(0xffffffffu, v, o);
    if ((tid & 31) == 0) sred[tid >> 5] = v;
    __syncthreads();
    if (tid < 32) {
        int w = sred[tid];
#pragma unroll
        for (int o = 16; o; o >>= 1) w += __shfl_down_sync(0xffffffffu, w, o);
        if (tid == 0) s_base = w;
    }
    __syncthreads();
    int i = blockIdx.x * SCAN_B + tid;
    if (i < N_NODES) g_off[i] = g_incl[i] - g_deg[i] + s_base;
}

__global__ void k_fill(const int* __restrict__ src, const int* __restrict__ dst) {
    int e = blockIdx.x * blockDim.x + threadIdx.x;
    if (e >= N_EDGES) return;
    int d = __ldg(dst + e);
    int pos = atomicAdd(&g_cursor[d], 1);
    g_csr_src[g_off[d] + pos] = __ldg(src + e);
}

// ---------------- K1: h1 = x @ W1 (128 -> 64), shared-staged ----------------
#define G1_STRIDE 20   // 16 cols + 4 pad (floats): conflict-free LDS.128
__global__ __launch_bounds__(256) void k_gemm1(const float* __restrict__ x,
                                               const float* __restrict__ W1) {
    __shared__ float sx[256 * G1_STRIDE];      // 20 KB
    __shared__ ulonglong2 sWc[16][16];         // 4 KB : [k][c4] = 4 out-ch
    int tid = threadIdx.x;
    int row0 = blockIdx.x * 256;
    int row = row0 + tid;

    unsigned long long acc[32];
#pragma unroll
    for (int i = 0; i < 32; i++) acc[i] = 0ull;

    for (int ch = 0; ch < IN_CH / 16; ch++) {   // 8 chunks of 16 k
        __syncthreads();
        {   // x tile: 256 rows x 16 cols, coalesced
            int c4 = tid & 3, r = tid >> 2;
#pragma unroll
            for (int j = 0; j < 4; j++) {
                int rr = r + j * 64;
                int gr = min(row0 + rr, N_NODES - 1);
                float4 v = __ldg(reinterpret_cast<const float4*>(
                                     x + (size_t)gr * IN_CH + ch * 16) + c4);
                *reinterpret_cast<float4*>(&sx[rr * G1_STRIDE + c4 * 4]) = v;
            }
        }
        {   // W chunk: 16 k-rows x 64 ch
            int k = tid >> 4, c4 = tid & 15;
            float4 w = __ldg(reinterpret_cast<const float4*>(
                                 W1 + (size_t)(ch * 16 + k) * HID_CH) + c4);
            *reinterpret_cast<float4*>(&sWc[k][c4]) = w;
        }
        __syncthreads();
#pragma unroll
        for (int k4 = 0; k4 < 4; k4++) {
            float4 xv = *reinterpret_cast<const float4*>(&sx[tid * G1_STRIDE + k4 * 4]);
#pragma unroll
            for (int j = 0; j < 4; j++) {
                float xs = (j == 0) ? xv.x : (j == 1) ? xv.y : (j == 2) ? xv.z : xv.w;
                unsigned long long xx = pack2(xs, xs);
                int k = k4 * 4 + j;
#pragma unroll
                for (int c4 = 0; c4 < 16; c4++) {
                    ulonglong2 w = sWc[k][c4];
                    acc[2 * c4 + 0] = fma2(xx, w.x, acc[2 * c4 + 0]);
                    acc[2 * c4 + 1] = fma2(xx, w.y, acc[2 * c4 + 1]);
                }
            }
        }
    }
    if (row < N_NODES) {
        ulonglong2* o = reinterpret_cast<ulonglong2*>(g_h1 + (size_t)row * HID_CH);
#pragma unroll
        for (int c4 = 0; c4 < 16; c4++) {
            ulonglong2 v; v.x = acc[2 * c4]; v.y = acc[2 * c4 + 1];
            o[c4] = v;
        }
    }
}

// ---------------- agg1: act1 = relu(A @ h1 + b1), warp/node, MLP-8 ----------------
__device__ __forceinline__ float2 ld2(int s, int lane) {
    float2 v = __ldg(reinterpret_cast<const float2*>(g_h1) + (size_t)s * 32 + lane);
    return v;
}
__global__ __launch_bounds__(256) void k_agg1(const float* __restrict__ b1) {
    int t = blockIdx.x * 256 + threadIdx.x;
    int node = t >> 5;
    if (node >= N_NODES) return;
    int lane = t & 31;

    int beg = g_off[node];
    int dg  = g_deg[node];

    float2 a0{0,0}, a1{0,0}, a2{0,0}, a3{0,0}, a4{0,0}, a5{0,0}, a6{0,0}, a7{0,0};
    for (int base = 0; base < dg; base += 32) {
        int rem = dg - base;                 // >= 1
        int idx = 0;
        if (lane < rem) idx = __ldg(g_csr_src + beg + base + lane);
#pragma unroll
        for (int k = 0; k < 32; k += 8) {
            if (k >= rem) break;             // warp-uniform
            int s0 = __shfl_sync(0xffffffffu, idx, k + 0);
            int s1 = __shfl_sync(0xffffffffu, idx, k + 1);
            int s2 = __shfl_sync(0xffffffffu, idx, k + 2);
            int s3 = __shfl_sync(0xffffffffu, idx, k + 3);
            int s4 = __shfl_sync(0xffffffffu, idx, k + 4);
            int s5 = __shfl_sync(0xffffffffu, idx, k + 5);
            int s6 = __shfl_sync(0xffffffffu, idx, k + 6);
            int s7 = __shfl_sync(0xffffffffu, idx, k + 7);
            { float2 v = ld2(s0, lane); a0.x += v.x; a0.y += v.y; }
            if (k + 1 < rem) { float2 v = ld2(s1, lane); a1.x += v.x; a1.y += v.y; }
            if (k + 2 < rem) { float2 v = ld2(s2, lane); a2.x += v.x; a2.y += v.y; }
            if (k + 3 < rem) { float2 v = ld2(s3, lane); a3.x += v.x; a3.y += v.y; }
            if (k + 4 < rem) { float2 v = ld2(s4, lane); a4.x += v.x; a4.y += v.y; }
            if (k + 5 < rem) { float2 v = ld2(s5, lane); a5.x += v.x; a5.y += v.y; }
            if (k + 6 < rem) { float2 v = ld2(s6, lane); a6.x += v.x; a6.y += v.y; }
            if (k + 7 < rem) { float2 v = ld2(s7, lane); a7.x += v.x; a7.y += v.y; }
        }
    }
    float2 acc;
    acc.x = ((a0.x + a1.x) + (a2.x + a3.x)) + ((a4.x + a5.x) + (a6.x + a7.x));
    acc.y = ((a0.y + a1.y) + (a2.y + a3.y)) + ((a4.y + a5.y) + (a6.y + a7.y));
    float2 b = reinterpret_cast<const float2*>(b1)[lane];
    acc.x = fmaxf(acc.x + b.x, 0.f);
    acc.y = fmaxf(acc.y + b.y, 0.f);
    reinterpret_cast<float2*>(g_act1 + (size_t)node * HID_CH)[lane] = acc;
}

// ---------------- K3: m2 = act1 @ W2 (64 -> 32), shared-staged ----------------
__global__ __launch_bounds__(256) void k_gemm2(const float* __restrict__ W2) {
    __shared__ float sx[256 * G1_STRIDE];      // 20 KB
    __shared__ ulonglong2 sWc[16][8];          // 2 KB
    int tid = threadIdx.x;
    int row0 = blockIdx.x * 256;
    int row = row0 + tid;

    unsigned long long acc[16];
#pragma unroll
    for (int i = 0; i < 16; i++) acc[i] = 0ull;

    for (int ch = 0; ch < HID_CH / 16; ch++) {   // 4 chunks of 16 k
        __syncthreads();
        {
            int c4 = tid & 3, r = tid >> 2;
#pragma unroll
            for (int j = 0; j < 4; j++) {
                int rr = r + j * 64;
                int gr = min(row0 + rr, N_NODES - 1);
                float4 v = *reinterpret_cast<const float4*>(
                    g_act1 + (size_t)gr * HID_CH + ch * 16 + c4 * 4);
                *reinterpret_cast<float4*>(&sx[rr * G1_STRIDE + c4 * 4]) = v;
            }
        }
        if (tid < 128) {
            int k = tid >> 3, c4 = tid & 7;
            float4 w = __ldg(reinterpret_cast<const float4*>(
                                 W2 + (size_t)(ch * 16 + k) * CLS_CH) + c4);
            *reinterpret_cast<float4*>(&sWc[k][c4]) = w;
        }
        __syncthreads();
#pragma unroll
        for (int k4 = 0; k4 < 4; k4++) {
            float4 xv = *reinterpret_cast<const float4*>(&sx[tid * G1_STRIDE + k4 * 4]);
#pragma unroll
            for (int j = 0; j < 4; j++) {
                float xs = (j == 0) ? xv.x : (j == 1) ? xv.y : (j == 2) ? xv.z : xv.w;
                unsigned long long xx = pack2(xs, xs);
                int k = k4 * 4 + j;
#pragma unroll
                for (int c4 = 0; c4 < 8; c4++) {
                    ulonglong2 w = sWc[k][c4];
                    acc[2 * c4 + 0] = fma2(xx, w.x, acc[2 * c4 + 0]);
                    acc[2 * c4 + 1] = fma2(xx, w.y, acc[2 * c4 + 1]);
                }
            }
        }
    }
    if (row < N_NODES) {
        ulonglong2* o = reinterpret_cast<ulonglong2*>(g_m2 + (size_t)row * CLS_CH);
#pragma unroll
        for (int c4 = 0; c4 < 8; c4++) {
            ulonglong2 v; v.x = acc[2 * c4]; v.y = acc[2 * c4 + 1];
            o[c4] = v;
        }
    }
}

// ---------------- agg2: out = sigmoid(A @ m2 + b2), warp/node, MLP-8 ----------------
__global__ __launch_bounds__(256) void k_agg2(const float* __restrict__ b2,
                                              float* __restrict__ out) {
    int t = blockIdx.x * 256 + threadIdx.x;
    int node = t >> 5;
    if (node >= N_NODES) return;
    int lane = t & 31;

    int beg = g_off[node];
    int dg  = g_deg[node];

    float a0 = 0.f, a1 = 0.f, a2 = 0.f, a3 = 0.f, a4 = 0.f, a5 = 0.f, a6 = 0.f, a7 = 0.f;
    for (int base = 0; base < dg; base += 32) {
        int rem = dg - base;
        int idx = 0;
        if (lane < rem) idx = __ldg(g_csr_src + beg + base + lane);
#pragma unroll
        for (int k = 0; k < 32; k += 8) {
            if (k >= rem) break;
            int s0 = __shfl_sync(0xffffffffu, idx, k + 0);
            int s1 = __shfl_sync(0xffffffffu, idx, k + 1);
            int s2 = __shfl_sync(0xffffffffu, idx, k + 2);
            int s3 = __shfl_sync(0xffffffffu, idx, k + 3);
            int s4 = __shfl_sync(0xffffffffu, idx, k + 4);
            int s5 = __shfl_sync(0xffffffffu, idx, k + 5);
            int s6 = __shfl_sync(0xffffffffu, idx, k + 6);
            int s7 = __shfl_sync(0xffffffffu, idx, k + 7);
            a0 += __ldg(g_m2 + (size_t)s0 * CLS_CH + lane);
            if (k + 1 < rem) a1 += __ldg(g_m2 + (size_t)s1 * CLS_CH + lane);
            if (k + 2 < rem) a2 += __ldg(g_m2 + (size_t)s2 * CLS_CH + lane);
            if (k + 3 < rem) a3 += __ldg(g_m2 + (size_t)s3 * CLS_CH + lane);
            if (k + 4 < rem) a4 += __ldg(g_m2 + (size_t)s4 * CLS_CH + lane);
            if (k + 5 < rem) a5 += __ldg(g_m2 + (size_t)s5 * CLS_CH + lane);
            if (k + 6 < rem) a6 += __ldg(g_m2 + (size_t)s6 * CLS_CH + lane);
            if (k + 7 < rem) a7 += __ldg(g_m2 + (size_t)s7 * CLS_CH + lane);
        }
    }
    float acc = ((a0 + a1) + (a2 + a3)) + ((a4 + a5) + (a6 + a7));
    float v = acc + __ldg(b2 + lane);
    out[(size_t)node * CLS_CH + lane] = 1.f / (1.f + __expf(-v));
}

extern "C" void kernel_launch(void* const* d_in, const int* in_sizes, int n_in,
                              void* d_out, int out_size) {
    const float* x  = (const float*)d_in[0];
    const int*   ei = (const int*)  d_in[1];
    const float* W1 = (const float*)d_in[2];
    const float* b1 = (const float*)d_in[3];
    const float* W2 = (const float*)d_in[4];
    const float* b2 = (const float*)d_in[5];
    float* out = (float*)d_out;
    const int* src = ei;
    const int* dst = ei + N_EDGES;

    // CSR build
    k_zero_cnt<<<(N_NODES + 255) / 256, 256>>>();
    k_hist<<<(N_EDGES + 255) / 256, 256>>>(dst);
    k_scan1<<<NB, SCAN_B>>>();
    k_scan23<<<NB, SCAN_B>>>();
    k_fill<<<(N_EDGES + 255) / 256, 256>>>(src, dst);

    // layer 1
    k_gemm1<<<(N_NODES + 255) / 256, 256>>>(x, W1);
    k_agg1<<<(N_NODES * 32 + 255) / 256, 256>>>(b1);
    // layer 2
    k_gemm2<<<(N_NODES + 255) / 256, 256>>>(W2);
    k_agg2<<<(N_NODES * 32 + 255) / 256, 256>>>(b2, out);
}